// round 6
// baseline (speedup 1.0000x reference)
#include <cuda_runtime.h>
#include <cstdint>

#define NROWS 409600
#define NIN   51200
#define NSEG  65536
#define DIM   512

// ---------------- scratch (static __device__ arrays: alloc-free rule) ----------
__device__ int   g_is64 = 1;        // detect only ever writes 0 -> replay-deterministic
__device__ int   g_counts[NSEG];
__device__ int   g_part[256];
__device__ int   g_pbase[256];
__device__ int   g_offsets[NSEG];
__device__ int   g_cursor[NSEG];
__device__ int   g_perm[NROWS];
__device__ float g_linw[DIM * DIM]; // tf32-rounded copy of lin_w

// ---------------- helpers ----------------
__device__ __forceinline__ float rna_tf32(float x) {
    uint32_t r;
    asm("cvt.rna.tf32.f32 %0, %1;" : "=r"(r) : "f"(x));
    return __uint_as_float(r);
}
__device__ __forceinline__ int load_idx(const void* idx, int i, int is64) {
    if (is64) return (int)((const long long*)idx)[i];
    return ((const int*)idx)[i];
}
__device__ __forceinline__ void cp16(uint32_t smem, const void* gmem) {
    asm volatile("cp.async.cg.shared.global [%0], [%1], 16;"
                 :: "r"(smem), "l"(gmem) : "memory");
}

// ---------------- prep kernels ----------------
__global__ void zero_detect_kernel(const unsigned int* w32) {
    int i = blockIdx.x * blockDim.x + threadIdx.x;
    if (i < NSEG) g_counts[i] = 0;
    if (i < 1024 && w32[2 * i + 1] != 0u) g_is64 = 0;
}
__global__ void hist_kernel(const void* idx) {
    int i = blockIdx.x * blockDim.x + threadIdx.x;
    if (i >= NROWS) return;
    atomicAdd(&g_counts[load_idx(idx, i, g_is64)], 1);
}
__global__ void scan1_kernel() {
    __shared__ int ws[8];
    int t = threadIdx.x;
    int v = g_counts[blockIdx.x * 256 + t];
    #pragma unroll
    for (int o = 16; o > 0; o >>= 1) v += __shfl_down_sync(0xFFFFFFFFu, v, o);
    if ((t & 31) == 0) ws[t >> 5] = v;
    __syncthreads();
    if (t == 0) {
        int s = 0;
        #pragma unroll
        for (int k = 0; k < 8; k++) s += ws[k];
        g_part[blockIdx.x] = s;
    }
}
__global__ void scan2_kernel() {
    __shared__ int ws[8];
    int t = threadIdx.x, lane = t & 31, wid = t >> 5;
    int v = g_part[t];
    int x = v;
    #pragma unroll
    for (int o = 1; o < 32; o <<= 1) {
        int y = __shfl_up_sync(0xFFFFFFFFu, x, o);
        if (lane >= o) x += y;
    }
    if (lane == 31) ws[wid] = x;
    __syncthreads();
    if (t < 8) {
        int s = ws[t];
        #pragma unroll
        for (int o = 1; o < 8; o <<= 1) {
            int y = __shfl_up_sync(0xFFu, s, o);
            if (t >= o) s += y;
        }
        ws[t] = s;
    }
    __syncthreads();
    int base = (wid > 0) ? ws[wid - 1] : 0;
    g_pbase[t] = base + x - v;
}
__global__ void scan3_kernel() {
    __shared__ int ws[8];
    int t = threadIdx.x, lane = t & 31, wid = t >> 5;
    int i = blockIdx.x * 256 + t;
    int v = g_counts[i];
    int x = v;
    #pragma unroll
    for (int o = 1; o < 32; o <<= 1) {
        int y = __shfl_up_sync(0xFFFFFFFFu, x, o);
        if (lane >= o) x += y;
    }
    if (lane == 31) ws[wid] = x;
    __syncthreads();
    if (t < 8) {
        int s = ws[t];
        #pragma unroll
        for (int o = 1; o < 8; o <<= 1) {
            int y = __shfl_up_sync(0xFFu, s, o);
            if (t >= o) s += y;
        }
        ws[t] = s;
    }
    __syncthreads();
    int base = (wid > 0) ? ws[wid - 1] : 0;
    int off = g_pbase[blockIdx.x] + base + x - v;
    g_offsets[i] = off;
    g_cursor[i]  = off;
}
__global__ void scatter_kernel(const void* idx) {
    int i = blockIdx.x * blockDim.x + threadIdx.x;
    if (i >= NROWS) return;
    int s = load_idx(idx, i, g_is64);
    int pos = atomicAdd(&g_cursor[s], 1);
    g_perm[pos] = i;
}
__global__ void roundw_kernel(const float* __restrict__ lw) {
    int i = blockIdx.x * blockDim.x + threadIdx.x;
    if (i < DIM * DIM) g_linw[i] = rna_tf32(lw[i]);
}

// ---------------- fused gather + GEMM --------------------------------------
// One block = 64 segments x full N=512 output tile.
// Phase 1: 16 warps x 4 segments gather w*h sums straight into SMEM A (tf32).
// Phase 2: A[64x512] @ lin_w^T with B double-buffered in BK=16 chunks.
#define MSEG 64
#define APAD 516                       // 512 + 4 pad words -> bank (4r+k)%32
#define BK   16
#define BPAD 20                        // 16 + 4 pad words -> bank (20n+k)%32
#define ASMW (MSEG * APAD)             // 33024 words
#define BSMW (DIM * BPAD)              // 10240 words per buffer
#define SMEM_BYTES ((ASMW + 2 * BSMW) * 4)   // 214016

__device__ __forceinline__ void mma_tf32(float& d0, float& d1, float& d2, float& d3,
                                         uint32_t a0, uint32_t a1, uint32_t a2, uint32_t a3,
                                         uint32_t b0, uint32_t b1) {
    asm volatile(
        "mma.sync.aligned.m16n8k8.row.col.f32.tf32.tf32.f32 "
        "{%0,%1,%2,%3}, {%4,%5,%6,%7}, {%8,%9}, {%0,%1,%2,%3};"
        : "+f"(d0), "+f"(d1), "+f"(d2), "+f"(d3)
        : "r"(a0), "r"(a1), "r"(a2), "r"(a3), "r"(b0), "r"(b1));
}

__global__ void __launch_bounds__(512, 1)
fused_kernel(const float* __restrict__ h, const float* __restrict__ w,
             const float* __restrict__ linb, float* __restrict__ out) {
    extern __shared__ float sm[];
    float* As = sm;                       // [MSEG][APAD]
    int tid = threadIdx.x, lane = tid & 31, wid = tid >> 5;
    const float4* hb = (const float4*)h;
    uint32_t sbase = (uint32_t)__cvta_generic_to_shared(sm);

    // ---------------- phase 1: gather into SMEM A ----------------
    for (int s = 0; s < 4; s++) {
        int m = wid * 4 + s;                       // block-local segment row
        int seg = blockIdx.x * MSEG + m;
        int start = g_offsets[seg];
        int cnt   = g_counts[seg];
        float4 a0 = {0.f, 0.f, 0.f, 0.f}, a1 = a0, a2 = a0, a3 = a0;

        auto accum2 = [&](int rowA, int rowB) {    // rowB < 0 => single
            float wv0 = __ldg(&w[rowA % NIN]);
            const float4* hp0 = hb + (size_t)rowA * (DIM / 4);
            float4 x0 = __ldg(hp0 + lane);
            float4 x1 = __ldg(hp0 + 32 + lane);
            float4 x2 = __ldg(hp0 + 64 + lane);
            float4 x3 = __ldg(hp0 + 96 + lane);
            float wv1 = 0.f;
            float4 y0 = x0, y1 = x1, y2 = x2, y3 = x3;
            if (rowB >= 0) {
                wv1 = __ldg(&w[rowB % NIN]);
                const float4* hp1 = hb + (size_t)rowB * (DIM / 4);
                y0 = __ldg(hp1 + lane);
                y1 = __ldg(hp1 + 32 + lane);
                y2 = __ldg(hp1 + 64 + lane);
                y3 = __ldg(hp1 + 96 + lane);
            }
            a0.x = fmaf(wv0, x0.x, a0.x); a0.y = fmaf(wv0, x0.y, a0.y);
            a0.z = fmaf(wv0, x0.z, a0.z); a0.w = fmaf(wv0, x0.w, a0.w);
            a1.x = fmaf(wv0, x1.x, a1.x); a1.y = fmaf(wv0, x1.y, a1.y);
            a1.z = fmaf(wv0, x1.z, a1.z); a1.w = fmaf(wv0, x1.w, a1.w);
            a2.x = fmaf(wv0, x2.x, a2.x); a2.y = fmaf(wv0, x2.y, a2.y);
            a2.z = fmaf(wv0, x2.z, a2.z); a2.w = fmaf(wv0, x2.w, a2.w);
            a3.x = fmaf(wv0, x3.x, a3.x); a3.y = fmaf(wv0, x3.y, a3.y);
            a3.z = fmaf(wv0, x3.z, a3.z); a3.w = fmaf(wv0, x3.w, a3.w);
            if (rowB >= 0) {
                a0.x = fmaf(wv1, y0.x, a0.x); a0.y = fmaf(wv1, y0.y, a0.y);
                a0.z = fmaf(wv1, y0.z, a0.z); a0.w = fmaf(wv1, y0.w, a0.w);
                a1.x = fmaf(wv1, y1.x, a1.x); a1.y = fmaf(wv1, y1.y, a1.y);
                a1.z = fmaf(wv1, y1.z, a1.z); a1.w = fmaf(wv1, y1.w, a1.w);
                a2.x = fmaf(wv1, y2.x, a2.x); a2.y = fmaf(wv1, y2.y, a2.y);
                a2.z = fmaf(wv1, y2.z, a2.z); a2.w = fmaf(wv1, y2.w, a2.w);
                a3.x = fmaf(wv1, y3.x, a3.x); a3.y = fmaf(wv1, y3.y, a3.y);
                a3.z = fmaf(wv1, y3.z, a3.z); a3.w = fmaf(wv1, y3.w, a3.w);
            }
        };

        if (cnt <= 32) {
            // 32-lane bitonic sort: deterministic ascending order, rows known
            // before any load -> deep MLP in the accumulate loop.
            int v = (lane < cnt) ? g_perm[start + lane] : 0x7FFFFFFF;
            #pragma unroll
            for (int k = 2; k <= 32; k <<= 1) {
                #pragma unroll
                for (int j = k >> 1; j > 0; j >>= 1) {
                    int p = __shfl_xor_sync(0xFFFFFFFFu, v, j);
                    bool up = ((lane & k) == 0);
                    bool lower = ((lane & j) == 0);
                    v = (lower == up) ? min(v, p) : max(v, p);
                }
            }
            int j = 0;
            for (; j + 2 <= cnt; j += 2) {
                int rA = __shfl_sync(0xFFFFFFFFu, v, j);
                int rB = __shfl_sync(0xFFFFFFFFu, v, j + 1);
                accum2(rA, rB);
            }
            if (j < cnt) accum2(__shfl_sync(0xFFFFFFFFu, v, j), -1);
        } else if (cnt <= 256) {
            int vals[8];
            int nslot = (cnt + 31) >> 5;
            #pragma unroll
            for (int t = 0; t < 8; t++) {
                int p = t * 32 + lane;
                vals[t] = (t < nslot && p < cnt) ? g_perm[start + p] : 0x7FFFFFFF;
            }
            for (int it = 0; it < cnt; it++) {
                int mmin = 0x7FFFFFFF, mt = -1;
                #pragma unroll
                for (int t = 0; t < 8; t++)
                    if (vals[t] < mmin) { mmin = vals[t]; mt = t; }
                int gm = __reduce_min_sync(0xFFFFFFFFu, mmin);
                if (mmin == gm && mt >= 0) vals[mt] = 0x7FFFFFFF;
                accum2(gm, -1);
            }
        } else {
            for (int j = 0; j < cnt; j++) accum2(g_perm[start + j], -1);
        }

        float* dst = As + (size_t)m * APAD;
        float4 o;
        o.x = rna_tf32(a0.x); o.y = rna_tf32(a0.y); o.z = rna_tf32(a0.z); o.w = rna_tf32(a0.w);
        *(float4*)(dst + 4 * lane) = o;
        o.x = rna_tf32(a1.x); o.y = rna_tf32(a1.y); o.z = rna_tf32(a1.z); o.w = rna_tf32(a1.w);
        *(float4*)(dst + 128 + 4 * lane) = o;
        o.x = rna_tf32(a2.x); o.y = rna_tf32(a2.y); o.z = rna_tf32(a2.z); o.w = rna_tf32(a2.w);
        *(float4*)(dst + 256 + 4 * lane) = o;
        o.x = rna_tf32(a3.x); o.y = rna_tf32(a3.y); o.z = rna_tf32(a3.z); o.w = rna_tf32(a3.w);
        *(float4*)(dst + 384 + 4 * lane) = o;
    }
    __syncthreads();

    // ---------------- phase 2: GEMM A @ lin_w^T + bias ----------------
    auto load_b = [&](int chunk, int buf) {        // B chunk: 512 x 16 floats
        uint32_t bs = sbase + (uint32_t)(ASMW + buf * BSMW) * 4;
        #pragma unroll
        for (int j = 0; j < 4; j++) {
            int e = j * 512 + tid;                 // 2048 float4
            int n = e >> 2, c4 = e & 3;
            cp16(bs + (uint32_t)(n * BPAD + c4 * 4) * 4,
                 g_linw + (size_t)n * DIM + chunk * BK + c4 * 4);
        }
        asm volatile("cp.async.commit_group;" ::: "memory");
    };

    int wm = (wid & 1) * 32;                       // 2 M-positions (warp tile 32x64)
    int wn = (wid >> 1) * 64;                      // 8 N-positions -> 512
    float acc[2][8][4];
    #pragma unroll
    for (int mi = 0; mi < 2; mi++)
        #pragma unroll
        for (int ni = 0; ni < 8; ni++)
            #pragma unroll
            for (int q = 0; q < 4; q++) acc[mi][ni][q] = 0.f;

    load_b(0, 0);
    const int NCH = DIM / BK;                      // 32
    int rq = lane >> 2, cq = lane & 3;
    for (int c = 0; c < NCH; c++) {
        if (c + 1 < NCH) {
            load_b(c + 1, (c + 1) & 1);
            asm volatile("cp.async.wait_group 1;" ::: "memory");
        } else {
            asm volatile("cp.async.wait_group 0;" ::: "memory");
        }
        __syncthreads();

        const uint32_t* Bs = (const uint32_t*)(sm + ASMW + (c & 1) * BSMW);
        const uint32_t* Aw = (const uint32_t*)As;
        #pragma unroll
        for (int ks = 0; ks < 2; ks++) {
            int k0 = c * BK + ks * 8;              // absolute K for A
            int kl = ks * 8;                       // local K for B chunk
            uint32_t bf[8][2];
            #pragma unroll
            for (int ni = 0; ni < 8; ni++) {
                int n = wn + ni * 8 + rq;
                bf[ni][0] = Bs[n * BPAD + kl + cq];
                bf[ni][1] = Bs[n * BPAD + kl + cq + 4];
            }
            #pragma unroll
            for (int mi = 0; mi < 2; mi++) {
                int r = wm + mi * 16 + rq;
                uint32_t fa0 = Aw[r * APAD + k0 + cq];
                uint32_t fa1 = Aw[(r + 8) * APAD + k0 + cq];
                uint32_t fa2 = Aw[r * APAD + k0 + cq + 4];
                uint32_t fa3 = Aw[(r + 8) * APAD + k0 + cq + 4];
                #pragma unroll
                for (int ni = 0; ni < 8; ni++)
                    mma_tf32(acc[mi][ni][0], acc[mi][ni][1], acc[mi][ni][2], acc[mi][ni][3],
                             fa0, fa1, fa2, fa3, bf[ni][0], bf[ni][1]);
            }
        }
        __syncthreads();
    }

    // epilogue: bias + store (f32 out)
    #pragma unroll
    for (int mi = 0; mi < 2; mi++) {
        int r0 = blockIdx.x * MSEG + wm + mi * 16 + rq;
        #pragma unroll
        for (int ni = 0; ni < 8; ni++) {
            int col = wn + ni * 8 + 2 * cq;
            float2 bv = __ldg((const float2*)(linb + col));
            float2 v0 = {acc[mi][ni][0] + bv.x, acc[mi][ni][1] + bv.y};
            float2 v1 = {acc[mi][ni][2] + bv.x, acc[mi][ni][3] + bv.y};
            *(float2*)(out + (size_t)r0 * DIM + col) = v0;
            *(float2*)(out + (size_t)(r0 + 8) * DIM + col) = v1;
        }
    }
}

// ---------------- launch ----------------
extern "C" void kernel_launch(void* const* d_in, const int* in_sizes, int n_in,
                              void* d_out, int out_size) {
    const float* h     = (const float*)d_in[0];
    const float* w     = (const float*)d_in[1];
    const float* lin_w = (const float*)d_in[2];
    const float* lin_b = (const float*)d_in[3];
    const void*  idx   = d_in[4];
    float* out = (float*)d_out;

    zero_detect_kernel<<<(NSEG + 255) / 256, 256>>>((const unsigned int*)idx);
    hist_kernel<<<(NROWS + 255) / 256, 256>>>(idx);
    scan1_kernel<<<256, 256>>>();
    scan2_kernel<<<1, 256>>>();
    scan3_kernel<<<256, 256>>>();
    scatter_kernel<<<(NROWS + 255) / 256, 256>>>(idx);
    roundw_kernel<<<(DIM * DIM + 255) / 256, 256>>>(lin_w);

    static int smem_set = 0;
    if (!smem_set) {
        cudaFuncSetAttribute(fused_kernel, cudaFuncAttributeMaxDynamicSharedMemorySize,
                             SMEM_BYTES);
        smem_set = 1;
    }
    fused_kernel<<<NSEG / MSEG, 512, SMEM_BYTES>>>(h, w, lin_b, out);
}

// round 7
// speedup vs baseline: 1.3053x; 1.3053x over previous
#include <cuda_runtime.h>
#include <cstdint>

#define NROWS 409600
#define NIN   51200
#define NSEG  65536
#define DIM   512

// ---------------- scratch (static __device__ arrays: alloc-free rule) ----------
__device__ int   g_is64 = 1;        // detect only ever writes 0 -> replay-deterministic
__device__ int   g_counts[NSEG];
__device__ int   g_part[256];
__device__ int   g_pbase[256];
__device__ int   g_offsets[NSEG];
__device__ int   g_cursor[NSEG];
__device__ int   g_perm[NROWS];
__device__ float g_agg[(size_t)NSEG * DIM];     // 134 MB, tf32-rounded
__device__ float g_linw[DIM * DIM];             // tf32-rounded copy of lin_w

// ---------------- helpers ----------------
__device__ __forceinline__ float rna_tf32(float x) {
    uint32_t r;
    asm("cvt.rna.tf32.f32 %0, %1;" : "=r"(r) : "f"(x));
    return __uint_as_float(r);
}
__device__ __forceinline__ int load_idx(const void* idx, int i, int is64) {
    if (is64) return (int)((const long long*)idx)[i];
    return ((const int*)idx)[i];
}
__device__ __forceinline__ void cp16(uint32_t smem, const void* gmem) {
    asm volatile("cp.async.cg.shared.global [%0], [%1], 16;"
                 :: "r"(smem), "l"(gmem) : "memory");
}

// ---------------- prep kernels ----------------
__global__ void zero_detect_kernel(const unsigned int* w32) {
    int i = blockIdx.x * blockDim.x + threadIdx.x;
    if (i < NSEG) g_counts[i] = 0;
    if (i < 1024 && w32[2 * i + 1] != 0u) g_is64 = 0;
}
__global__ void hist_kernel(const void* idx) {
    int i = blockIdx.x * blockDim.x + threadIdx.x;
    if (i >= NROWS) return;
    atomicAdd(&g_counts[load_idx(idx, i, g_is64)], 1);
}
__global__ void scan1_kernel() {
    __shared__ int ws[8];
    int t = threadIdx.x;
    int v = g_counts[blockIdx.x * 256 + t];
    #pragma unroll
    for (int o = 16; o > 0; o >>= 1) v += __shfl_down_sync(0xFFFFFFFFu, v, o);
    if ((t & 31) == 0) ws[t >> 5] = v;
    __syncthreads();
    if (t == 0) {
        int s = 0;
        #pragma unroll
        for (int k = 0; k < 8; k++) s += ws[k];
        g_part[blockIdx.x] = s;
    }
}
__global__ void scan2_kernel() {
    __shared__ int ws[8];
    int t = threadIdx.x, lane = t & 31, wid = t >> 5;
    int v = g_part[t];
    int x = v;
    #pragma unroll
    for (int o = 1; o < 32; o <<= 1) {
        int y = __shfl_up_sync(0xFFFFFFFFu, x, o);
        if (lane >= o) x += y;
    }
    if (lane == 31) ws[wid] = x;
    __syncthreads();
    if (t < 8) {
        int s = ws[t];
        #pragma unroll
        for (int o = 1; o < 8; o <<= 1) {
            int y = __shfl_up_sync(0xFFu, s, o);
            if (t >= o) s += y;
        }
        ws[t] = s;
    }
    __syncthreads();
    int base = (wid > 0) ? ws[wid - 1] : 0;
    g_pbase[t] = base + x - v;
}
__global__ void scan3_kernel() {
    __shared__ int ws[8];
    int t = threadIdx.x, lane = t & 31, wid = t >> 5;
    int i = blockIdx.x * 256 + t;
    int v = g_counts[i];
    int x = v;
    #pragma unroll
    for (int o = 1; o < 32; o <<= 1) {
        int y = __shfl_up_sync(0xFFFFFFFFu, x, o);
        if (lane >= o) x += y;
    }
    if (lane == 31) ws[wid] = x;
    __syncthreads();
    if (t < 8) {
        int s = ws[t];
        #pragma unroll
        for (int o = 1; o < 8; o <<= 1) {
            int y = __shfl_up_sync(0xFFu, s, o);
            if (t >= o) s += y;
        }
        ws[t] = s;
    }
    __syncthreads();
    int base = (wid > 0) ? ws[wid - 1] : 0;
    int off = g_pbase[blockIdx.x] + base + x - v;
    g_offsets[i] = off;
    g_cursor[i]  = off;
}
__global__ void scatter_kernel(const void* idx) {
    int i = blockIdx.x * blockDim.x + threadIdx.x;
    if (i >= NROWS) return;
    int s = load_idx(idx, i, g_is64);
    int pos = atomicAdd(&g_cursor[s], 1);
    g_perm[pos] = i;
}
__global__ void roundw_kernel(const float* __restrict__ lw) {
    int i = blockIdx.x * blockDim.x + threadIdx.x;
    if (i < DIM * DIM) g_linw[i] = rna_tf32(lw[i]);
}

// ---------------- gather-sum: one warp per segment, deterministic order --------
// 4-row unrolled loop: 16 outstanding LDG.128 per warp. Tail uses exact-width
// 2/1-row steps => no wasted traffic, ascending order preserved.
__global__ void __launch_bounds__(256) gather_kernel(const float* __restrict__ h,
                                                     const float* __restrict__ w) {
    int warp = (blockIdx.x * blockDim.x + threadIdx.x) >> 5;
    int lane = threadIdx.x & 31;
    if (warp >= NSEG) return;
    int start = g_offsets[warp];
    int cnt   = g_counts[warp];
    float4 a0 = {0.f, 0.f, 0.f, 0.f}, a1 = a0, a2 = a0, a3 = a0;
    const float4* hb = (const float4*)h;

    auto fma_row = [&](float wv, float4 x0, float4 x1, float4 x2, float4 x3) {
        a0.x = fmaf(wv, x0.x, a0.x); a0.y = fmaf(wv, x0.y, a0.y);
        a0.z = fmaf(wv, x0.z, a0.z); a0.w = fmaf(wv, x0.w, a0.w);
        a1.x = fmaf(wv, x1.x, a1.x); a1.y = fmaf(wv, x1.y, a1.y);
        a1.z = fmaf(wv, x1.z, a1.z); a1.w = fmaf(wv, x1.w, a1.w);
        a2.x = fmaf(wv, x2.x, a2.x); a2.y = fmaf(wv, x2.y, a2.y);
        a2.z = fmaf(wv, x2.z, a2.z); a2.w = fmaf(wv, x2.w, a2.w);
        a3.x = fmaf(wv, x3.x, a3.x); a3.y = fmaf(wv, x3.y, a3.y);
        a3.z = fmaf(wv, x3.z, a3.z); a3.w = fmaf(wv, x3.w, a3.w);
    };
    auto accum4 = [&](int r0, int r1, int r2, int r3) {
        float w0 = __ldg(&w[r0 % NIN]);
        float w1 = __ldg(&w[r1 % NIN]);
        float w2 = __ldg(&w[r2 % NIN]);
        float w3 = __ldg(&w[r3 % NIN]);
        const float4* p0 = hb + (size_t)r0 * (DIM / 4);
        const float4* p1 = hb + (size_t)r1 * (DIM / 4);
        const float4* p2 = hb + (size_t)r2 * (DIM / 4);
        const float4* p3 = hb + (size_t)r3 * (DIM / 4);
        float4 x00 = __ldg(p0 + lane),      x01 = __ldg(p0 + 32 + lane);
        float4 x02 = __ldg(p0 + 64 + lane), x03 = __ldg(p0 + 96 + lane);
        float4 x10 = __ldg(p1 + lane),      x11 = __ldg(p1 + 32 + lane);
        float4 x12 = __ldg(p1 + 64 + lane), x13 = __ldg(p1 + 96 + lane);
        float4 x20 = __ldg(p2 + lane),      x21 = __ldg(p2 + 32 + lane);
        float4 x22 = __ldg(p2 + 64 + lane), x23 = __ldg(p2 + 96 + lane);
        float4 x30 = __ldg(p3 + lane),      x31 = __ldg(p3 + 32 + lane);
        float4 x32 = __ldg(p3 + 64 + lane), x33 = __ldg(p3 + 96 + lane);
        fma_row(w0, x00, x01, x02, x03);
        fma_row(w1, x10, x11, x12, x13);
        fma_row(w2, x20, x21, x22, x23);
        fma_row(w3, x30, x31, x32, x33);
    };
    auto accum2 = [&](int r0, int r1) {
        float w0 = __ldg(&w[r0 % NIN]);
        float w1 = __ldg(&w[r1 % NIN]);
        const float4* p0 = hb + (size_t)r0 * (DIM / 4);
        const float4* p1 = hb + (size_t)r1 * (DIM / 4);
        float4 x00 = __ldg(p0 + lane),      x01 = __ldg(p0 + 32 + lane);
        float4 x02 = __ldg(p0 + 64 + lane), x03 = __ldg(p0 + 96 + lane);
        float4 x10 = __ldg(p1 + lane),      x11 = __ldg(p1 + 32 + lane);
        float4 x12 = __ldg(p1 + 64 + lane), x13 = __ldg(p1 + 96 + lane);
        fma_row(w0, x00, x01, x02, x03);
        fma_row(w1, x10, x11, x12, x13);
    };
    auto accum1 = [&](int r0) {
        float w0 = __ldg(&w[r0 % NIN]);
        const float4* p0 = hb + (size_t)r0 * (DIM / 4);
        float4 x00 = __ldg(p0 + lane),      x01 = __ldg(p0 + 32 + lane);
        float4 x02 = __ldg(p0 + 64 + lane), x03 = __ldg(p0 + 96 + lane);
        fma_row(w0, x00, x01, x02, x03);
    };

    if (cnt <= 32) {
        // 32-lane bitonic sort of row ids (ascending): deterministic order,
        // all rows known before any load -> deep MLP.
        int v = (lane < cnt) ? g_perm[start + lane] : 0x7FFFFFFF;
        #pragma unroll
        for (int k = 2; k <= 32; k <<= 1) {
            #pragma unroll
            for (int j = k >> 1; j > 0; j >>= 1) {
                int p = __shfl_xor_sync(0xFFFFFFFFu, v, j);
                bool up = ((lane & k) == 0);
                bool lower = ((lane & j) == 0);
                v = (lower == up) ? min(v, p) : max(v, p);
            }
        }
        int j = 0;
        for (; j + 4 <= cnt; j += 4) {
            int r0 = __shfl_sync(0xFFFFFFFFu, v, j);
            int r1 = __shfl_sync(0xFFFFFFFFu, v, j + 1);
            int r2 = __shfl_sync(0xFFFFFFFFu, v, j + 2);
            int r3 = __shfl_sync(0xFFFFFFFFu, v, j + 3);
            accum4(r0, r1, r2, r3);
        }
        if (j + 2 <= cnt) {
            int r0 = __shfl_sync(0xFFFFFFFFu, v, j);
            int r1 = __shfl_sync(0xFFFFFFFFu, v, j + 1);
            accum2(r0, r1);
            j += 2;
        }
        if (j < cnt) accum1(__shfl_sync(0xFFFFFFFFu, v, j));
    } else if (cnt <= 256) {
        // min-extraction fallback (rare)
        int vals[8];
        int nslot = (cnt + 31) >> 5;
        #pragma unroll
        for (int t = 0; t < 8; t++) {
            int p = t * 32 + lane;
            vals[t] = (t < nslot && p < cnt) ? g_perm[start + p] : 0x7FFFFFFF;
        }
        for (int it = 0; it < cnt; it++) {
            int m = 0x7FFFFFFF, mt = -1;
            #pragma unroll
            for (int t = 0; t < 8; t++)
                if (vals[t] < m) { m = vals[t]; mt = t; }
            int gm = __reduce_min_sync(0xFFFFFFFFu, m);
            if (m == gm && mt >= 0) vals[mt] = 0x7FFFFFFF;
            accum1(gm);
        }
    } else {
        for (int j = 0; j < cnt; j++) accum1(g_perm[start + j]);
    }

    float4* dst = (float4*)(g_agg + (size_t)warp * DIM);
    float4 o;
    o.x = rna_tf32(a0.x); o.y = rna_tf32(a0.y); o.z = rna_tf32(a0.z); o.w = rna_tf32(a0.w);
    dst[lane] = o;
    o.x = rna_tf32(a1.x); o.y = rna_tf32(a1.y); o.z = rna_tf32(a1.z); o.w = rna_tf32(a1.w);
    dst[32 + lane] = o;
    o.x = rna_tf32(a2.x); o.y = rna_tf32(a2.y); o.z = rna_tf32(a2.z); o.w = rna_tf32(a2.w);
    dst[64 + lane] = o;
    o.x = rna_tf32(a3.x); o.y = rna_tf32(a3.y); o.z = rna_tf32(a3.z); o.w = rna_tf32(a3.w);
    dst[96 + lane] = o;
}

// ---------------- tf32 mma.sync GEMM: out = agg @ lin_w^T + b -------------------
// BM=128, BN=256, BK=32, 512 threads. Grid = (ntile, mtile): ntile pair of one
// mtile co-resident -> A-tile second read hits L2.
#define BK 32
#define PADW 36
#define ATILEW (128 * PADW)
#define BTILEW (256 * PADW)
#define SMEM_BYTES ((2 * ATILEW + 2 * BTILEW) * 4)   // 110592

__device__ __forceinline__ void mma_tf32(float& d0, float& d1, float& d2, float& d3,
                                         uint32_t a0, uint32_t a1, uint32_t a2, uint32_t a3,
                                         uint32_t b0, uint32_t b1) {
    asm volatile(
        "mma.sync.aligned.m16n8k8.row.col.f32.tf32.tf32.f32 "
        "{%0,%1,%2,%3}, {%4,%5,%6,%7}, {%8,%9}, {%0,%1,%2,%3};"
        : "+f"(d0), "+f"(d1), "+f"(d2), "+f"(d3)
        : "r"(a0), "r"(a1), "r"(a2), "r"(a3), "r"(b0), "r"(b1));
}

__global__ void __launch_bounds__(512, 1)
gemm_kernel(const float* __restrict__ linb, float* __restrict__ out) {
    extern __shared__ float sm[];
    int tid = threadIdx.x, lane = tid & 31, wid = tid >> 5;
    int ntile = blockIdx.x, mtile = blockIdx.y;
    const float* Ag = g_agg  + (size_t)mtile * 128 * DIM;
    const float* Bg = g_linw + (size_t)ntile * 256 * DIM;

    uint32_t sbase = (uint32_t)__cvta_generic_to_shared(sm);

    auto load_tile = [&](int kb, int buf) {
        uint32_t as = sbase + (uint32_t)(buf * ATILEW) * 4;
        uint32_t bs = sbase + (uint32_t)(2 * ATILEW + buf * BTILEW) * 4;
        #pragma unroll
        for (int j = 0; j < 2; j++) {
            int e = j * 512 + tid;
            int row = e >> 3, c4 = e & 7;
            cp16(as + (uint32_t)(row * PADW + c4 * 4) * 4,
                 Ag + (size_t)row * DIM + kb * BK + c4 * 4);
        }
        #pragma unroll
        for (int j = 0; j < 4; j++) {
            int e = j * 512 + tid;
            int row = e >> 3, c4 = e & 7;
            cp16(bs + (uint32_t)(row * PADW + c4 * 4) * 4,
                 Bg + (size_t)row * DIM + kb * BK + c4 * 4);
        }
        asm volatile("cp.async.commit_group;" ::: "memory");
    };

    int wm = (wid & 1) * 64;
    int wn = (wid >> 1) * 32;
    float acc[4][4][4];
    #pragma unroll
    for (int mi = 0; mi < 4; mi++)
        #pragma unroll
        for (int ni = 0; ni < 4; ni++)
            #pragma unroll
            for (int q = 0; q < 4; q++) acc[mi][ni][q] = 0.f;

    load_tile(0, 0);
    const int NKB = DIM / BK;
    for (int kb = 0; kb < NKB; kb++) {
        if (kb + 1 < NKB) {
            load_tile(kb + 1, (kb + 1) & 1);
            asm volatile("cp.async.wait_group 1;" ::: "memory");
        } else {
            asm volatile("cp.async.wait_group 0;" ::: "memory");
        }
        __syncthreads();

        int buf = kb & 1;
        const uint32_t* As = (const uint32_t*)(sm + buf * ATILEW);
        const uint32_t* Bs = (const uint32_t*)(sm + 2 * ATILEW + buf * BTILEW);
        int rq = lane >> 2, cq = lane & 3;
        #pragma unroll
        for (int ks = 0; ks < BK / 8; ks++) {
            int k0 = ks * 8;
            uint32_t bf[4][2];
            #pragma unroll
            for (int ni = 0; ni < 4; ni++) {
                int n = wn + ni * 8 + rq;
                bf[ni][0] = Bs[n * PADW + k0 + cq];
                bf[ni][1] = Bs[n * PADW + k0 + cq + 4];
            }
            #pragma unroll
            for (int mi = 0; mi < 4; mi++) {
                int r = wm + mi * 16 + rq;
                uint32_t fa0 = As[r * PADW + k0 + cq];
                uint32_t fa1 = As[(r + 8) * PADW + k0 + cq];
                uint32_t fa2 = As[r * PADW + k0 + cq + 4];
                uint32_t fa3 = As[(r + 8) * PADW + k0 + cq + 4];
                #pragma unroll
                for (int ni = 0; ni < 4; ni++)
                    mma_tf32(acc[mi][ni][0], acc[mi][ni][1], acc[mi][ni][2], acc[mi][ni][3],
                             fa0, fa1, fa2, fa3, bf[ni][0], bf[ni][1]);
            }
        }
        __syncthreads();
    }

    int rq = lane >> 2, cq = lane & 3;
    #pragma unroll
    for (int mi = 0; mi < 4; mi++) {
        int r0 = mtile * 128 + wm + mi * 16 + rq;
        #pragma unroll
        for (int ni = 0; ni < 4; ni++) {
            int col = ntile * 256 + wn + ni * 8 + 2 * cq;
            float2 bv = __ldg((const float2*)(linb + col));
            float2 v0 = {acc[mi][ni][0] + bv.x, acc[mi][ni][1] + bv.y};
            float2 v1 = {acc[mi][ni][2] + bv.x, acc[mi][ni][3] + bv.y};
            *(float2*)(out + (size_t)r0 * DIM + col) = v0;
            *(float2*)(out + (size_t)(r0 + 8) * DIM + col) = v1;
        }
    }
}

// ---------------- launch ----------------
extern "C" void kernel_launch(void* const* d_in, const int* in_sizes, int n_in,
                              void* d_out, int out_size) {
    const float* h     = (const float*)d_in[0];
    const float* w     = (const float*)d_in[1];
    const float* lin_w = (const float*)d_in[2];
    const float* lin_b = (const float*)d_in[3];
    const void*  idx   = d_in[4];
    float* out = (float*)d_out;

    zero_detect_kernel<<<(NSEG + 255) / 256, 256>>>((const unsigned int*)idx);
    hist_kernel<<<(NROWS + 255) / 256, 256>>>(idx);
    scan1_kernel<<<256, 256>>>();
    scan2_kernel<<<1, 256>>>();
    scan3_kernel<<<256, 256>>>();
    scatter_kernel<<<(NROWS + 255) / 256, 256>>>(idx);
    roundw_kernel<<<(DIM * DIM + 255) / 256, 256>>>(lin_w);
    gather_kernel<<<NSEG / 8, 256>>>(h, w);

    static int smem_set = 0;
    if (!smem_set) {
        cudaFuncSetAttribute(gemm_kernel, cudaFuncAttributeMaxDynamicSharedMemorySize,
                             SMEM_BYTES);
        smem_set = 1;
    }
    gemm_kernel<<<dim3(DIM / 256, NSEG / 128, 1), 512, SMEM_BYTES>>>(lin_b, out);
}

// round 8
// speedup vs baseline: 1.6734x; 1.2820x over previous
#include <cuda_runtime.h>
#include <cuda_fp16.h>
#include <cstdint>

#define NROWS 409600
#define NIN   51200
#define NSEG  65536
#define DIM   512

// ---------------- scratch (static __device__ arrays: alloc-free rule) ----------
__device__ int    g_is64 = 1;       // detect only ever writes 0 -> replay-deterministic
__device__ int    g_counts[NSEG];
__device__ int    g_part[256];
__device__ int    g_pbase[256];
__device__ int    g_offsets[NSEG];
__device__ int    g_cursor[NSEG];
__device__ int    g_perm[NROWS];
__device__ __half g_aggh[(size_t)NSEG * DIM];   // 67 MB, fp16-rounded segment sums
__device__ __half g_linwh[DIM * DIM];           // fp16 copy of lin_w

// ---------------- helpers ----------------
__device__ __forceinline__ int load_idx(const void* idx, int i, int is64) {
    if (is64) return (int)((const long long*)idx)[i];
    return ((const int*)idx)[i];
}
__device__ __forceinline__ void cp16(uint32_t smem, const void* gmem) {
    asm volatile("cp.async.cg.shared.global [%0], [%1], 16;"
                 :: "r"(smem), "l"(gmem) : "memory");
}

// ---------------- prep kernels ----------------
__global__ void zero_detect_kernel(const unsigned int* w32) {
    int i = blockIdx.x * blockDim.x + threadIdx.x;
    if (i < NSEG) g_counts[i] = 0;
    if (i < 1024 && w32[2 * i + 1] != 0u) g_is64 = 0;
}
__global__ void hist_kernel(const void* idx) {
    int i = blockIdx.x * blockDim.x + threadIdx.x;
    if (i >= NROWS) return;
    atomicAdd(&g_counts[load_idx(idx, i, g_is64)], 1);
}
__global__ void scan1_kernel() {
    __shared__ int ws[8];
    int t = threadIdx.x;
    int v = g_counts[blockIdx.x * 256 + t];
    #pragma unroll
    for (int o = 16; o > 0; o >>= 1) v += __shfl_down_sync(0xFFFFFFFFu, v, o);
    if ((t & 31) == 0) ws[t >> 5] = v;
    __syncthreads();
    if (t == 0) {
        int s = 0;
        #pragma unroll
        for (int k = 0; k < 8; k++) s += ws[k];
        g_part[blockIdx.x] = s;
    }
}
__global__ void scan2_kernel() {
    __shared__ int ws[8];
    int t = threadIdx.x, lane = t & 31, wid = t >> 5;
    int v = g_part[t];
    int x = v;
    #pragma unroll
    for (int o = 1; o < 32; o <<= 1) {
        int y = __shfl_up_sync(0xFFFFFFFFu, x, o);
        if (lane >= o) x += y;
    }
    if (lane == 31) ws[wid] = x;
    __syncthreads();
    if (t < 8) {
        int s = ws[t];
        #pragma unroll
        for (int o = 1; o < 8; o <<= 1) {
            int y = __shfl_up_sync(0xFFu, s, o);
            if (t >= o) s += y;
        }
        ws[t] = s;
    }
    __syncthreads();
    int base = (wid > 0) ? ws[wid - 1] : 0;
    g_pbase[t] = base + x - v;
}
__global__ void scan3_kernel() {
    __shared__ int ws[8];
    int t = threadIdx.x, lane = t & 31, wid = t >> 5;
    int i = blockIdx.x * 256 + t;
    int v = g_counts[i];
    int x = v;
    #pragma unroll
    for (int o = 1; o < 32; o <<= 1) {
        int y = __shfl_up_sync(0xFFFFFFFFu, x, o);
        if (lane >= o) x += y;
    }
    if (lane == 31) ws[wid] = x;
    __syncthreads();
    if (t < 8) {
        int s = ws[t];
        #pragma unroll
        for (int o = 1; o < 8; o <<= 1) {
            int y = __shfl_up_sync(0xFFu, s, o);
            if (t >= o) s += y;
        }
        ws[t] = s;
    }
    __syncthreads();
    int base = (wid > 0) ? ws[wid - 1] : 0;
    int off = g_pbase[blockIdx.x] + base + x - v;
    g_offsets[i] = off;
    g_cursor[i]  = off;
}
__global__ void scatter_kernel(const void* idx) {
    int i = blockIdx.x * blockDim.x + threadIdx.x;
    if (i >= NROWS) return;
    int s = load_idx(idx, i, g_is64);
    int pos = atomicAdd(&g_cursor[s], 1);
    g_perm[pos] = i;
}
__global__ void roundw_kernel(const float* __restrict__ lw) {
    int i = blockIdx.x * blockDim.x + threadIdx.x;
    if (i < DIM * DIM) g_linwh[i] = __float2half_rn(lw[i]);
}

// ---------------- gather-sum: one warp per segment, deterministic order --------
__global__ void __launch_bounds__(256) gather_kernel(const float* __restrict__ h,
                                                     const float* __restrict__ w) {
    int warp = (blockIdx.x * blockDim.x + threadIdx.x) >> 5;
    int lane = threadIdx.x & 31;
    if (warp >= NSEG) return;
    int start = g_offsets[warp];
    int cnt   = g_counts[warp];
    float4 a0 = {0.f, 0.f, 0.f, 0.f}, a1 = a0, a2 = a0, a3 = a0;
    const float4* hb = (const float4*)h;

    auto fma_row = [&](float wv, float4 x0, float4 x1, float4 x2, float4 x3) {
        a0.x = fmaf(wv, x0.x, a0.x); a0.y = fmaf(wv, x0.y, a0.y);
        a0.z = fmaf(wv, x0.z, a0.z); a0.w = fmaf(wv, x0.w, a0.w);
        a1.x = fmaf(wv, x1.x, a1.x); a1.y = fmaf(wv, x1.y, a1.y);
        a1.z = fmaf(wv, x1.z, a1.z); a1.w = fmaf(wv, x1.w, a1.w);
        a2.x = fmaf(wv, x2.x, a2.x); a2.y = fmaf(wv, x2.y, a2.y);
        a2.z = fmaf(wv, x2.z, a2.z); a2.w = fmaf(wv, x2.w, a2.w);
        a3.x = fmaf(wv, x3.x, a3.x); a3.y = fmaf(wv, x3.y, a3.y);
        a3.z = fmaf(wv, x3.z, a3.z); a3.w = fmaf(wv, x3.w, a3.w);
    };
    auto accum4 = [&](int r0, int r1, int r2, int r3) {
        float w0 = __ldg(&w[r0 % NIN]);
        float w1 = __ldg(&w[r1 % NIN]);
        float w2 = __ldg(&w[r2 % NIN]);
        float w3 = __ldg(&w[r3 % NIN]);
        const float4* p0 = hb + (size_t)r0 * (DIM / 4);
        const float4* p1 = hb + (size_t)r1 * (DIM / 4);
        const float4* p2 = hb + (size_t)r2 * (DIM / 4);
        const float4* p3 = hb + (size_t)r3 * (DIM / 4);
        float4 x00 = __ldg(p0 + lane),      x01 = __ldg(p0 + 32 + lane);
        float4 x02 = __ldg(p0 + 64 + lane), x03 = __ldg(p0 + 96 + lane);
        float4 x10 = __ldg(p1 + lane),      x11 = __ldg(p1 + 32 + lane);
        float4 x12 = __ldg(p1 + 64 + lane), x13 = __ldg(p1 + 96 + lane);
        float4 x20 = __ldg(p2 + lane),      x21 = __ldg(p2 + 32 + lane);
        float4 x22 = __ldg(p2 + 64 + lane), x23 = __ldg(p2 + 96 + lane);
        float4 x30 = __ldg(p3 + lane),      x31 = __ldg(p3 + 32 + lane);
        float4 x32 = __ldg(p3 + 64 + lane), x33 = __ldg(p3 + 96 + lane);
        fma_row(w0, x00, x01, x02, x03);
        fma_row(w1, x10, x11, x12, x13);
        fma_row(w2, x20, x21, x22, x23);
        fma_row(w3, x30, x31, x32, x33);
    };
    auto accum2 = [&](int r0, int r1) {
        float w0 = __ldg(&w[r0 % NIN]);
        float w1 = __ldg(&w[r1 % NIN]);
        const float4* p0 = hb + (size_t)r0 * (DIM / 4);
        const float4* p1 = hb + (size_t)r1 * (DIM / 4);
        float4 x00 = __ldg(p0 + lane),      x01 = __ldg(p0 + 32 + lane);
        float4 x02 = __ldg(p0 + 64 + lane), x03 = __ldg(p0 + 96 + lane);
        float4 x10 = __ldg(p1 + lane),      x11 = __ldg(p1 + 32 + lane);
        float4 x12 = __ldg(p1 + 64 + lane), x13 = __ldg(p1 + 96 + lane);
        fma_row(w0, x00, x01, x02, x03);
        fma_row(w1, x10, x11, x12, x13);
    };
    auto accum1 = [&](int r0) {
        float w0 = __ldg(&w[r0 % NIN]);
        const float4* p0 = hb + (size_t)r0 * (DIM / 4);
        float4 x00 = __ldg(p0 + lane),      x01 = __ldg(p0 + 32 + lane);
        float4 x02 = __ldg(p0 + 64 + lane), x03 = __ldg(p0 + 96 + lane);
        fma_row(w0, x00, x01, x02, x03);
    };

    if (cnt <= 32) {
        int v = (lane < cnt) ? g_perm[start + lane] : 0x7FFFFFFF;
        #pragma unroll
        for (int k = 2; k <= 32; k <<= 1) {
            #pragma unroll
            for (int j = k >> 1; j > 0; j >>= 1) {
                int p = __shfl_xor_sync(0xFFFFFFFFu, v, j);
                bool up = ((lane & k) == 0);
                bool lower = ((lane & j) == 0);
                v = (lower == up) ? min(v, p) : max(v, p);
            }
        }
        int j = 0;
        for (; j + 4 <= cnt; j += 4) {
            int r0 = __shfl_sync(0xFFFFFFFFu, v, j);
            int r1 = __shfl_sync(0xFFFFFFFFu, v, j + 1);
            int r2 = __shfl_sync(0xFFFFFFFFu, v, j + 2);
            int r3 = __shfl_sync(0xFFFFFFFFu, v, j + 3);
            accum4(r0, r1, r2, r3);
        }
        if (j + 2 <= cnt) {
            int r0 = __shfl_sync(0xFFFFFFFFu, v, j);
            int r1 = __shfl_sync(0xFFFFFFFFu, v, j + 1);
            accum2(r0, r1);
            j += 2;
        }
        if (j < cnt) accum1(__shfl_sync(0xFFFFFFFFu, v, j));
    } else if (cnt <= 256) {
        int vals[8];
        int nslot = (cnt + 31) >> 5;
        #pragma unroll
        for (int t = 0; t < 8; t++) {
            int p = t * 32 + lane;
            vals[t] = (t < nslot && p < cnt) ? g_perm[start + p] : 0x7FFFFFFF;
        }
        for (int it = 0; it < cnt; it++) {
            int m = 0x7FFFFFFF, mt = -1;
            #pragma unroll
            for (int t = 0; t < 8; t++)
                if (vals[t] < m) { m = vals[t]; mt = t; }
            int gm = __reduce_min_sync(0xFFFFFFFFu, m);
            if (m == gm && mt >= 0) vals[mt] = 0x7FFFFFFF;
            accum1(gm);
        }
    } else {
        for (int j = 0; j < cnt; j++) accum1(g_perm[start + j]);
    }

    // fp16 RN conversion (same 11-bit significand as tf32) + 8B stores
    __half2* dsth = (__half2*)(g_aggh + (size_t)warp * DIM);
    dsth[2 * lane]           = __floats2half2_rn(a0.x, a0.y);
    dsth[2 * lane + 1]       = __floats2half2_rn(a0.z, a0.w);
    dsth[64 + 2 * lane]      = __floats2half2_rn(a1.x, a1.y);
    dsth[64 + 2 * lane + 1]  = __floats2half2_rn(a1.z, a1.w);
    dsth[128 + 2 * lane]     = __floats2half2_rn(a2.x, a2.y);
    dsth[128 + 2 * lane + 1] = __floats2half2_rn(a2.z, a2.w);
    dsth[192 + 2 * lane]     = __floats2half2_rn(a3.x, a3.y);
    dsth[192 + 2 * lane + 1] = __floats2half2_rn(a3.z, a3.w);
}

// ---------------- fp16 mma.sync GEMM: out = agg @ lin_w^T + b -------------------
// BM=128, BN=256, BK=32 halves, 512 threads, m16n8k16.f16 with f32 accum.
// Half rows padded to 40 halves (20 words): bank (20*rq+cq)%32 all distinct.
#define BK 32
#define PADH 40
#define ATILEB (128 * PADH * 2)            // 10240 bytes
#define BTILEB (256 * PADH * 2)            // 20480 bytes
#define SMEM_BYTES (2 * ATILEB + 2 * BTILEB)   // 61440

__device__ __forceinline__ void mma_f16(float& d0, float& d1, float& d2, float& d3,
                                        uint32_t a0, uint32_t a1, uint32_t a2, uint32_t a3,
                                        uint32_t b0, uint32_t b1) {
    asm volatile(
        "mma.sync.aligned.m16n8k16.row.col.f32.f16.f16.f32 "
        "{%0,%1,%2,%3}, {%4,%5,%6,%7}, {%8,%9}, {%0,%1,%2,%3};"
        : "+f"(d0), "+f"(d1), "+f"(d2), "+f"(d3)
        : "r"(a0), "r"(a1), "r"(a2), "r"(a3), "r"(b0), "r"(b1));
}

__global__ void __launch_bounds__(512, 1)
gemm_kernel(const float* __restrict__ linb, float* __restrict__ out) {
    extern __shared__ char sm[];
    int tid = threadIdx.x, lane = tid & 31, wid = tid >> 5;
    int ntile = blockIdx.x, mtile = blockIdx.y;
    const __half* Ag = g_aggh  + (size_t)mtile * 128 * DIM;
    const __half* Bg = g_linwh + (size_t)ntile * 256 * DIM;

    uint32_t sbase = (uint32_t)__cvta_generic_to_shared(sm);

    auto load_tile = [&](int kb, int buf) {
        uint32_t as = sbase + (uint32_t)(buf * ATILEB);
        uint32_t bs = sbase + (uint32_t)(2 * ATILEB + buf * BTILEB);
        {   // A: 128 rows x 32 halves = 512 x 16B chunks (1/thread)
            int row = tid >> 2, c = tid & 3;
            cp16(as + (uint32_t)(row * PADH + c * 8) * 2,
                 Ag + (size_t)row * DIM + kb * BK + c * 8);
        }
        #pragma unroll
        for (int j = 0; j < 2; j++) {      // B: 256 x 32 halves = 1024 chunks
            int e = j * 512 + tid;
            int n = e >> 2, c = e & 3;
            cp16(bs + (uint32_t)(n * PADH + c * 8) * 2,
                 Bg + (size_t)n * DIM + kb * BK + c * 8);
        }
        asm volatile("cp.async.commit_group;" ::: "memory");
    };

    int wm = (wid & 1) * 64;
    int wn = (wid >> 1) * 32;
    float acc[4][4][4];
    #pragma unroll
    for (int mi = 0; mi < 4; mi++)
        #pragma unroll
        for (int ni = 0; ni < 4; ni++)
            #pragma unroll
            for (int q = 0; q < 4; q++) acc[mi][ni][q] = 0.f;

    load_tile(0, 0);
    const int NKB = DIM / BK;              // 16
    int rq = lane >> 2, cq = lane & 3;
    for (int kb = 0; kb < NKB; kb++) {
        if (kb + 1 < NKB) {
            load_tile(kb + 1, (kb + 1) & 1);
            asm volatile("cp.async.wait_group 1;" ::: "memory");
        } else {
            asm volatile("cp.async.wait_group 0;" ::: "memory");
        }
        __syncthreads();

        int buf = kb & 1;
        const uint32_t* As = (const uint32_t*)(sm + buf * ATILEB);
        const uint32_t* Bs = (const uint32_t*)(sm + 2 * ATILEB + buf * BTILEB);
        #pragma unroll
        for (int ks = 0; ks < BK / 16; ks++) {     // 2 K-steps of 16
            int k0 = ks * 8;                       // word offset (16 halves)
            uint32_t bf[4][2];
            #pragma unroll
            for (int ni = 0; ni < 4; ni++) {
                int n = wn + ni * 8 + rq;
                bf[ni][0] = Bs[n * (PADH / 2) + k0 + cq];
                bf[ni][1] = Bs[n * (PADH / 2) + k0 + cq + 4];
            }
            #pragma unroll
            for (int mi = 0; mi < 4; mi++) {
                int r = wm + mi * 16 + rq;
                uint32_t fa0 = As[r * (PADH / 2) + k0 + cq];
                uint32_t fa1 = As[(r + 8) * (PADH / 2) + k0 + cq];
                uint32_t fa2 = As[r * (PADH / 2) + k0 + cq + 4];
                uint32_t fa3 = As[(r + 8) * (PADH / 2) + k0 + cq + 4];
                #pragma unroll
                for (int ni = 0; ni < 4; ni++)
                    mma_f16(acc[mi][ni][0], acc[mi][ni][1], acc[mi][ni][2], acc[mi][ni][3],
                            fa0, fa1, fa2, fa3, bf[ni][0], bf[ni][1]);
            }
        }
        __syncthreads();
    }

    // epilogue: bias + store (f32 out)
    #pragma unroll
    for (int mi = 0; mi < 4; mi++) {
        int r0 = mtile * 128 + wm + mi * 16 + rq;
        #pragma unroll
        for (int ni = 0; ni < 4; ni++) {
            int col = ntile * 256 + wn + ni * 8 + 2 * cq;
            float2 bv = __ldg((const float2*)(linb + col));
            float2 v0 = {acc[mi][ni][0] + bv.x, acc[mi][ni][1] + bv.y};
            float2 v1 = {acc[mi][ni][2] + bv.x, acc[mi][ni][3] + bv.y};
            *(float2*)(out + (size_t)r0 * DIM + col) = v0;
            *(float2*)(out + (size_t)(r0 + 8) * DIM + col) = v1;
        }
    }
}

// ---------------- launch ----------------
extern "C" void kernel_launch(void* const* d_in, const int* in_sizes, int n_in,
                              void* d_out, int out_size) {
    const float* h     = (const float*)d_in[0];
    const float* w     = (const float*)d_in[1];
    const float* lin_w = (const float*)d_in[2];
    const float* lin_b = (const float*)d_in[3];
    const void*  idx   = d_in[4];
    float* out = (float*)d_out;

    zero_detect_kernel<<<(NSEG + 255) / 256, 256>>>((const unsigned int*)idx);
    hist_kernel<<<(NROWS + 255) / 256, 256>>>(idx);
    scan1_kernel<<<256, 256>>>();
    scan2_kernel<<<1, 256>>>();
    scan3_kernel<<<256, 256>>>();
    scatter_kernel<<<(NROWS + 255) / 256, 256>>>(idx);
    roundw_kernel<<<(DIM * DIM + 255) / 256, 256>>>(lin_w);
    gather_kernel<<<NSEG / 8, 256>>>(h, w);

    static int smem_set = 0;
    if (!smem_set) {
        cudaFuncSetAttribute(gemm_kernel, cudaFuncAttributeMaxDynamicSharedMemorySize,
                             SMEM_BYTES);
        smem_set = 1;
    }
    gemm_kernel<<<dim3(DIM / 256, NSEG / 128, 1), 512, SMEM_BYTES>>>(lin_b, out);
}